// round 8
// baseline (speedup 1.0000x reference)
#include <cuda_runtime.h>

// x (B,N,1) f32, indices (2,NNZ) i32, values (NNZ,) f32, bias (M,1) f32
//   -> out (B,M,1) f32
#define NN    100000
#define MM    100000
#define NNZ   3200000
#define BB    32
#define CHUNK 512
#define NCHUNK ((MM + CHUNK - 1) / CHUNK)   // 196

// ---- device scratch (static, no allocs) -----------------------------------
__device__ float g_xt[(size_t)NN * BB];      // x transposed: (N, B)
__device__ int   g_count[MM];                // per-dst degree
__device__ int   g_start[MM + 1];            // CSR row starts
__device__ int   g_cursor[MM];               // reorder write cursors
__device__ int   g_chunkoff[NCHUNK];
__device__ int   g_chunksum[NCHUNK];
__device__ int2  g_edge[NNZ];                // (src, val-as-int) grouped by dst

// ---------------------------------------------------------------------------
// 1) transpose x (B,N) -> xt (N,B); zero g_count. Block (32,8), 4 rows/thread.
// ---------------------------------------------------------------------------
__global__ void k_transpose_in(const float* __restrict__ x) {
    __shared__ float tile[32][33];
    const int n0 = blockIdx.x * 32;
    const int tx = threadIdx.x, ty = threadIdx.y;

    #pragma unroll
    for (int j = 0; j < 4; j++) {
        const int b = ty + 8 * j;
        tile[b][tx] = x[(size_t)b * NN + n0 + tx];
    }
    const int tid = blockIdx.x * 256 + ty * 32 + tx;   // 800k threads >= MM
    if (tid < MM) g_count[tid] = 0;
    __syncthreads();
    #pragma unroll
    for (int j = 0; j < 4; j++) {
        const int n = n0 + ty + 8 * j;
        g_xt[(size_t)n * BB + tx] = tile[tx][ty + 8 * j];
    }
}

// ---------------------------------------------------------------------------
// 2) histogram of dst (4 edges/thread via int4; NNZ % 4 == 0)
// ---------------------------------------------------------------------------
__global__ void k_hist(const int* __restrict__ indices) {
    const int t = blockIdx.x * blockDim.x + threadIdx.x;
    if (t >= NNZ / 4) return;
    const int4 d = reinterpret_cast<const int4*>(indices + NNZ)[t];
    atomicAdd(&g_count[d.x], 1);
    atomicAdd(&g_count[d.y], 1);
    atomicAdd(&g_count[d.z], 1);
    atomicAdd(&g_count[d.w], 1);
}

// ---------------------------------------------------------------------------
// 3) scan (3 small kernels, proven correct in R7)
// ---------------------------------------------------------------------------
__global__ void k_scan_a() {
    __shared__ int sm[CHUNK];
    const int t = threadIdx.x;
    const int idx = blockIdx.x * CHUNK + t;
    sm[t] = (idx < MM) ? g_count[idx] : 0;
    __syncthreads();
    for (int d = CHUNK / 2; d > 0; d >>= 1) {
        if (t < d) sm[t] += sm[t + d];
        __syncthreads();
    }
    if (t == 0) g_chunksum[blockIdx.x] = sm[0];
}

__global__ void k_scan_b() {
    __shared__ int sm[256];
    const int t = threadIdx.x;
    int v = (t < NCHUNK) ? g_chunksum[t] : 0;
    sm[t] = v;
    __syncthreads();
    for (int d = 1; d < 256; d <<= 1) {
        int u = (t >= d) ? sm[t - d] : 0;
        __syncthreads();
        sm[t] += u;
        __syncthreads();
    }
    if (t < NCHUNK) g_chunkoff[t] = sm[t] - v;   // exclusive
}

__global__ void k_scan_c() {
    __shared__ int sm[CHUNK];
    const int t = threadIdx.x;
    const int idx = blockIdx.x * CHUNK + t;
    const int v = (idx < MM) ? g_count[idx] : 0;
    sm[t] = v;
    __syncthreads();
    for (int d = 1; d < CHUNK; d <<= 1) {
        int u = (t >= d) ? sm[t - d] : 0;
        __syncthreads();
        sm[t] += u;
        __syncthreads();
    }
    if (idx < MM) {
        const int s = g_chunkoff[blockIdx.x] + sm[t] - v;
        g_start[idx]  = s;
        g_cursor[idx] = s;
    }
    if (blockIdx.x == 0 && t == 0) g_start[MM] = NNZ;
}

// ---------------------------------------------------------------------------
// 4) reorder edges into dst-grouped order, payload (src, val) as int2
// ---------------------------------------------------------------------------
__global__ void k_reorder(const int* __restrict__ indices,
                          const float* __restrict__ values) {
    const int e = blockIdx.x * blockDim.x + threadIdx.x;
    if (e >= NNZ) return;
    const int src = indices[e];
    const int dst = indices[NNZ + e];
    const int pos = atomicAdd(&g_cursor[dst], 1);
    g_edge[pos] = make_int2(src, __float_as_int(values[e]));
}

// ---------------------------------------------------------------------------
// 5) accumulate + fused output: one warp per 4 consecutive dsts, lane = batch.
//    Edge records read via uniform-address broadcast LDG (no shuffles).
//    Final float4 store writes out[b][m0..m0+3] (+bias) directly.
// ---------------------------------------------------------------------------
__global__ void k_accum(const float* __restrict__ bias,
                        float* __restrict__ out) {
    const int warp = (blockIdx.x * blockDim.x + threadIdx.x) >> 5;
    const int lane = threadIdx.x & 31;
    const int m0 = warp * 4;
    if (m0 >= MM) return;

    float acc[4];
    #pragma unroll
    for (int q = 0; q < 4; q++) {
        const int s    = g_start[m0 + q];
        const int eend = g_start[m0 + q + 1];
        float a0 = 0.f, a1 = 0.f, a2 = 0.f, a3 = 0.f;
        int e = s;
        for (; e + 4 <= eend; e += 4) {
            // Uniform-address loads: HW broadcast, mostly L1 hits.
            const int2 e0 = g_edge[e + 0];
            const int2 e1 = g_edge[e + 1];
            const int2 e2 = g_edge[e + 2];
            const int2 e3 = g_edge[e + 3];
            // 4 independent coalesced 128B gathers (L2 hits).
            const float x0 = g_xt[(size_t)e0.x * BB + lane];
            const float x1 = g_xt[(size_t)e1.x * BB + lane];
            const float x2 = g_xt[(size_t)e2.x * BB + lane];
            const float x3 = g_xt[(size_t)e3.x * BB + lane];
            a0 = fmaf(__int_as_float(e0.y), x0, a0);
            a1 = fmaf(__int_as_float(e1.y), x1, a1);
            a2 = fmaf(__int_as_float(e2.y), x2, a2);
            a3 = fmaf(__int_as_float(e3.y), x3, a3);
        }
        for (; e < eend; e++) {
            const int2 ee = g_edge[e];
            a0 = fmaf(__int_as_float(ee.y),
                      g_xt[(size_t)ee.x * BB + lane], a0);
        }
        acc[q] = (a0 + a1) + (a2 + a3);
    }

    const float4 bv = *reinterpret_cast<const float4*>(bias + m0);
    float4 r;
    r.x = acc[0] + bv.x;
    r.y = acc[1] + bv.y;
    r.z = acc[2] + bv.z;
    r.w = acc[3] + bv.w;
    // out[b][m0..m0+3]: 16B per lane, 512B fully-used sectors per warp.
    *reinterpret_cast<float4*>(out + (size_t)lane * MM + m0) = r;
}

// ---------------------------------------------------------------------------
extern "C" void kernel_launch(void* const* d_in, const int* in_sizes, int n_in,
                              void* d_out, int out_size) {
    const float* x       = (const float*)d_in[0];   // (B, N, 1)
    const int*   indices = (const int*)  d_in[1];   // (2, NNZ)
    const float* values  = (const float*)d_in[2];   // (NNZ,)
    const float* bias    = (const float*)d_in[3];   // (M, 1)
    float*       out     = (float*)d_out;           // (B, M, 1)
    (void)in_sizes; (void)n_in; (void)out_size;

    // 1) transpose in + zero counts
    k_transpose_in<<<NN / 32, dim3(32, 8)>>>(x);
    // 2) histogram
    k_hist<<<(NNZ / 4 + 255) / 256, 256>>>(indices);
    // 3) scan
    k_scan_a<<<NCHUNK, CHUNK>>>();
    k_scan_b<<<1, 256>>>();
    k_scan_c<<<NCHUNK, CHUNK>>>();
    // 4) reorder into dst-grouped CSR
    k_reorder<<<(NNZ + 255) / 256, 256>>>(indices, values);
    // 5) accumulate + fused transpose-out (+bias): MM/4 warps
    {
        const int warps = MM / 4;                 // 25000
        const int threads = 256;                  // 8 warps/block
        const int blocks = (warps * 32 + threads - 1) / threads;  // 3125
        k_accum<<<blocks, threads>>>(bias, out);
    }
}

// round 9
// speedup vs baseline: 1.5067x; 1.5067x over previous
#include <cuda_runtime.h>

// x (B,N,1) f32, indices (2,NNZ) i32, values (NNZ,) f32, bias (M,1) f32
//   -> out (B,M,1) f32
#define NN   100000
#define MM   100000
#define NNZ  3200000
#define BB   32
// NN, MM are exact multiples of 32 (3125 tiles).

// Scratch in batch-contiguous layout:
// xt[n*32 + b] = x[b*N + n];  yt[m*32 + b] accumulates, then transposed out.
__device__ float g_xt[(size_t)NN * BB];
__device__ float g_yt[(size_t)MM * BB];

// ---------------------------------------------------------------------------
// Kernel 1: transpose x (B,N) -> xt (N,B) and zero yt.
// Block (32,4): each thread handles 8 rows => 8 loads in flight (MLP=8).
// ---------------------------------------------------------------------------
__global__ void k_transpose_in(const float* __restrict__ x) {
    __shared__ float tile[32][33];
    const int n0 = blockIdx.x * 32;
    const int tx = threadIdx.x;     // n_local on load, b on store
    const int ty = threadIdx.y;     // 0..3

    #pragma unroll
    for (int j = 0; j < 8; j++) {
        const int b = ty + 4 * j;
        tile[b][tx] = x[(size_t)b * NN + n0 + tx];        // coalesced over tx
    }
    __syncthreads();
    #pragma unroll
    for (int j = 0; j < 8; j++) {
        const int n = n0 + ty + 4 * j;
        g_xt[(size_t)n * BB + tx] = tile[tx][ty + 4 * j]; // coalesced, tx=b
        g_yt[(size_t)n * BB + tx] = 0.0f;                 // zero accumulator
    }
}

// ---------------------------------------------------------------------------
// Kernel 2: edge scatter — EXACT R3 structure (best measured). 8 threads per
// edge, each owns a float4 of the 32 batches: one coalesced 128B gather from
// xt, one vector reduction red.global.add.v4.f32 into yt.
// ---------------------------------------------------------------------------
__global__ void k_scatter(const int* __restrict__ indices,
                          const float* __restrict__ values) {
    const long long t = (long long)blockIdx.x * blockDim.x + threadIdx.x;
    const long long e = t >> 3;        // edge id
    const int       q = (int)(t & 7);  // which float4 of the 32 batches
    if (e >= NNZ) return;

    const int   src = indices[e];
    const int   dst = indices[(long long)NNZ + e];
    const float v   = values[e];

    const float4 xv = reinterpret_cast<const float4*>(g_xt)[(size_t)src * 8 + q];
    const float4 c  = make_float4(v * xv.x, v * xv.y, v * xv.z, v * xv.w);

    float4* p = reinterpret_cast<float4*>(g_yt) + (size_t)dst * 8 + q;
    asm volatile("red.global.add.v4.f32 [%0], {%1, %2, %3, %4};"
                 :: "l"(p), "f"(c.x), "f"(c.y), "f"(c.z), "f"(c.w)
                 : "memory");
}

// ---------------------------------------------------------------------------
// Kernel 3: transpose yt (M,B) -> out (B,M) + bias. Block (32,4), 8/thread.
// ---------------------------------------------------------------------------
__global__ void k_transpose_out(float* __restrict__ out,
                                const float* __restrict__ bias) {
    __shared__ float tile[32][33];
    const int m0 = blockIdx.x * 32;
    const int tx = threadIdx.x;
    const int ty = threadIdx.y;

    #pragma unroll
    for (int j = 0; j < 8; j++) {
        const int m = m0 + ty + 4 * j;
        tile[ty + 4 * j][tx] = g_yt[(size_t)m * BB + tx];  // coalesced, tx=b
    }
    __syncthreads();
    const float bv = bias[m0 + tx];
    #pragma unroll
    for (int j = 0; j < 8; j++) {
        const int b = ty + 4 * j;
        out[(size_t)b * MM + m0 + tx] = tile[tx][b] + bv;  // coalesced, tx=m
    }
}

extern "C" void kernel_launch(void* const* d_in, const int* in_sizes, int n_in,
                              void* d_out, int out_size) {
    const float* x       = (const float*)d_in[0];   // (B, N, 1)
    const int*   indices = (const int*)  d_in[1];   // (2, NNZ)
    const float* values  = (const float*)d_in[2];   // (NNZ,)
    const float* bias    = (const float*)d_in[3];   // (M, 1)
    float*       out     = (float*)d_out;           // (B, M, 1)

    (void)in_sizes; (void)n_in; (void)out_size;

    {   // 1) transpose x -> xt, zero yt
        dim3 blk(32, 4);
        k_transpose_in<<<NN / 32, blk>>>(x);
    }
    {   // 2) edge scatter: NNZ * 8 threads (exact R3 config)
        const long long total = (long long)NNZ * 8;
        const int threads = 256;
        const int blocks = (int)((total + threads - 1) / threads);
        k_scatter<<<blocks, threads>>>(indices, values);
    }
    {   // 3) transpose yt -> out (+bias)
        dim3 blk(32, 4);
        k_transpose_out<<<MM / 32, blk>>>(out, bias);
    }
}

// round 10
// speedup vs baseline: 1.5255x; 1.0125x over previous
#include <cuda_runtime.h>

// x (B,N,1) f32, indices (2,NNZ) i32, values (NNZ,) f32, bias (M,1) f32
//   -> out (B,M,1) f32
#define NN   100000
#define MM   100000
#define NNZ  3200000
#define BB   32
#define NF4  (NN / 4)          // 25000 float4 per batch row
#define MF4  (MM / 4)

// Scratch in batch-contiguous layout:
// xt[n*32 + b] = x[b*N + n];  yt[m*32 + b] accumulates, then transposed out.
__device__ float g_xt[(size_t)NN * BB];
__device__ float g_yt[(size_t)MM * BB];

// ---------------------------------------------------------------------------
// Kernel 1: transpose x (B,N) -> xt (N,B), zero yt. float4 on both global
// sides. Tile: 32 b-rows x 128 n-cols. Block 256 threads, 4 slots each.
// smem tile[n_local][b], pitch 33 -> conflict-free both phases.
// ---------------------------------------------------------------------------
__global__ void k_transpose_in(const float* __restrict__ x) {
    __shared__ float tile[128][33];
    const int tid = threadIdx.x;
    const int c4_base = blockIdx.x * 32;       // float4 column base
    const int n0 = c4_base * 4;                // element column base

    // Load phase: thread owns b = tid>>3, c4 = (tid&7) + 8i.
    const int b_ld  = tid >> 3;
    const int c4_lo = tid & 7;
    #pragma unroll
    for (int i = 0; i < 4; i++) {
        const int c4l = c4_lo + 8 * i;                 // 0..31 within tile
        const int c4g = c4_base + c4l;
        if (c4g < NF4) {
            const float4 v =
                reinterpret_cast<const float4*>(x)[(size_t)b_ld * NF4 + c4g];
            tile[4 * c4l + 0][b_ld] = v.x;
            tile[4 * c4l + 1][b_ld] = v.y;
            tile[4 * c4l + 2][b_ld] = v.z;
            tile[4 * c4l + 3][b_ld] = v.w;
        }
    }
    __syncthreads();

    // Store phase: thread owns n_local = (tid>>3) + 32i, b4 = tid&7.
    const int b4 = tid & 7;
    #pragma unroll
    for (int i = 0; i < 4; i++) {
        const int nl = (tid >> 3) + 32 * i;            // 0..127
        const int n  = n0 + nl;
        if (n < NN) {
            float4 v;
            v.x = tile[nl][0 + 0];  // placeholder overwritten below
            v.x = tile[nl][4 * b4 + 0] * 0.0f;         // (avoid compiler fuss)
            v.x = tile[nl][4 * b4 + 0];
            v.y = tile[nl][4 * b4 + 1];
            v.z = tile[nl][4 * b4 + 2];
            v.w = tile[nl][4 * b4 + 3];
            // wait—tile second index is b (0..31); 4*b4+k selects 4 b's. OK.
            reinterpret_cast<float4*>(g_xt)[(size_t)n * 8 + b4] = v;
            reinterpret_cast<float4*>(g_yt)[(size_t)n * 8 + b4] =
                make_float4(0.f, 0.f, 0.f, 0.f);
        }
    }
}

// ---------------------------------------------------------------------------
// Kernel 2: edge scatter — EXACT R3/R9 structure (best measured). 8 threads
// per edge; one coalesced 128B gather from xt, one red.global.add.v4.f32.
// ---------------------------------------------------------------------------
__global__ void k_scatter(const int* __restrict__ indices,
                          const float* __restrict__ values) {
    const long long t = (long long)blockIdx.x * blockDim.x + threadIdx.x;
    const long long e = t >> 3;        // edge id
    const int       q = (int)(t & 7);  // which float4 of the 32 batches
    if (e >= NNZ) return;

    const int   src = indices[e];
    const int   dst = indices[(long long)NNZ + e];
    const float v   = values[e];

    const float4 xv = reinterpret_cast<const float4*>(g_xt)[(size_t)src * 8 + q];
    const float4 c  = make_float4(v * xv.x, v * xv.y, v * xv.z, v * xv.w);

    float4* p = reinterpret_cast<float4*>(g_yt) + (size_t)dst * 8 + q;
    asm volatile("red.global.add.v4.f32 [%0], {%1, %2, %3, %4};"
                 :: "l"(p), "f"(c.x), "f"(c.y), "f"(c.z), "f"(c.w)
                 : "memory");
}

// ---------------------------------------------------------------------------
// Kernel 3: transpose yt (M,B) -> out (B,M) + bias. float4 both sides.
// Tile: 128 m-rows x 32 b-cols; smem tile[b][m_local], pitch 129.
// ---------------------------------------------------------------------------
__global__ void k_transpose_out(float* __restrict__ out,
                                const float* __restrict__ bias) {
    __shared__ float tile[32][129];
    const int tid = threadIdx.x;
    const int m0 = blockIdx.x * 128;

    // Load phase: thread owns m_local = (tid>>3) + 32i, b4 = tid&7.
    const int b4 = tid & 7;
    #pragma unroll
    for (int i = 0; i < 4; i++) {
        const int ml = (tid >> 3) + 32 * i;            // 0..127
        const int m  = m0 + ml;
        if (m < MM) {
            const float4 v =
                reinterpret_cast<const float4*>(g_yt)[(size_t)m * 8 + b4];
            tile[4 * b4 + 0][ml] = v.x;
            tile[4 * b4 + 1][ml] = v.y;
            tile[4 * b4 + 2][ml] = v.z;
            tile[4 * b4 + 3][ml] = v.w;
        }
    }
    __syncthreads();

    // Store phase: thread owns b = tid>>3, m4 = (tid&7) + 8i.
    const int b_st  = tid >> 3;
    const int m4_lo = tid & 7;
    #pragma unroll
    for (int i = 0; i < 4; i++) {
        const int m4l = m4_lo + 8 * i;                 // 0..31 float4 within tile
        const int m4g = (m0 >> 2) + m4l;               // global float4 index
        if (m4g < MF4) {
            const int me = 4 * m4l;                    // element offset in tile
            const float4 bv =
                reinterpret_cast<const float4*>(bias)[m4g];
            float4 r;
            r.x = tile[b_st][me + 0] + bv.x;
            r.y = tile[b_st][me + 1] + bv.y;
            r.z = tile[b_st][me + 2] + bv.z;
            r.w = tile[b_st][me + 3] + bv.w;
            reinterpret_cast<float4*>(out)[(size_t)b_st * MF4 + m4g] = r;
        }
    }
}

extern "C" void kernel_launch(void* const* d_in, const int* in_sizes, int n_in,
                              void* d_out, int out_size) {
    const float* x       = (const float*)d_in[0];   // (B, N, 1)
    const int*   indices = (const int*)  d_in[1];   // (2, NNZ)
    const float* values  = (const float*)d_in[2];   // (NNZ,)
    const float* bias    = (const float*)d_in[3];   // (M, 1)
    float*       out     = (float*)d_out;           // (B, M, 1)

    (void)in_sizes; (void)n_in; (void)out_size;

    {   // 1) transpose x -> xt, zero yt. 128 n per block.
        const int blocks = (NF4 + 31) / 32;            // 782
        k_transpose_in<<<blocks, 256>>>(x);
    }
    {   // 2) edge scatter: NNZ * 8 threads (proven config)
        const long long total = (long long)NNZ * 8;
        const int threads = 256;
        const int blocks = (int)((total + threads - 1) / threads);
        k_scatter<<<blocks, threads>>>(indices, values);
    }
    {   // 3) transpose yt -> out (+bias). 128 m per block.
        const int blocks = (MF4 + 31) / 32;            // 782
        k_transpose_out<<<blocks, 256>>>(out, bias);
    }
}